// round 4
// baseline (speedup 1.0000x reference)
#include <cuda_runtime.h>

#define FULLMASK 0xFFFFFFFFu
#define KNN 16
#define GB 256                       // bins per axis
#define NB2 (GB * GB)
#define XLO (-6.0f)
#define BINW (12.0f / 256.0f)        // 0.046875
#define BSCALE (256.0f / 12.0f)
#define PAD 64
#define NCAP 32768
#define RBIG 3.0e38f

// ---- global scratch (no allocation allowed) ----
__device__ __align__(16) int g_hist[NB2];
__device__ __align__(16) int g_cnt[NB2];
__device__ __align__(16) int g_binstart[NB2 + 1];
__device__ float g_sx[NCAP];
__device__ float g_sy[NCAP];
__device__ float g_ssq[NCAP];
__device__ int   g_sorig[NCAP];

static __device__ __forceinline__ int bin1(float v) {
    int b = (int)((v - XLO) * BSCALE);
    return min(max(b, 0), GB - 1);
}

// ---- packed f32x2 helpers ----
static __device__ __forceinline__ unsigned long long fma2(unsigned long long a,
                                                          unsigned long long b,
                                                          unsigned long long c) {
    unsigned long long d;
    asm("fma.rn.f32x2 %0, %1, %2, %3;" : "=l"(d) : "l"(a), "l"(b), "l"(c));
    return d;
}
static __device__ __forceinline__ unsigned long long pack2(float lo, float hi) {
    unsigned long long v;
    asm("mov.b64 %0, {%1, %2};"
        : "=l"(v) : "r"(__float_as_uint(lo)), "r"(__float_as_uint(hi)));
    return v;
}
static __device__ __forceinline__ void unpack2(unsigned long long v, float &lo, float &hi) {
    unsigned a, b;
    asm("mov.b64 {%0, %1}, %2;" : "=r"(a), "=r"(b) : "l"(v));
    lo = __uint_as_float(a);
    hi = __uint_as_float(b);
}

// ================= setup kernels =================
__global__ void zero_kernel() {
    int i = blockIdx.x * blockDim.x + threadIdx.x;
    if (i < NB2) { g_hist[i] = 0; g_cnt[i] = 0; }
}

__global__ void hist_kernel(const float* __restrict__ p, int n) {
    int i = blockIdx.x * blockDim.x + threadIdx.x;
    if (i < n) {
        float x = p[3 * i];
        float y = p[3 * i + 1];
        atomicAdd(&g_hist[(bin1(y) << 8) | bin1(x)], 1);
    }
}

// exclusive prefix over 65536 bins: 1024 threads x 64 bins each
__global__ void prefix_kernel() {
    __shared__ int wsum[32];
    const int tid = threadIdx.x;
    const int lane = tid & 31;
    const int wid = tid >> 5;
    const int4* h4 = reinterpret_cast<const int4*>(g_hist);

    int s = 0;
#pragma unroll
    for (int j = 0; j < 16; j++) {
        int4 v = h4[tid * 16 + j];
        s += v.x + v.y + v.z + v.w;
    }
    int x = s;
#pragma unroll
    for (int d = 1; d < 32; d <<= 1) {
        int y = __shfl_up_sync(FULLMASK, x, d);
        if (lane >= d) x += y;
    }
    if (lane == 31) wsum[wid] = x;
    __syncthreads();
    if (tid < 32) {
        int w = wsum[tid];
#pragma unroll
        for (int d = 1; d < 32; d <<= 1) {
            int y = __shfl_up_sync(FULLMASK, w, d);
            if (tid >= d) w += y;
        }
        wsum[tid] = w;
    }
    __syncthreads();
    int run = x - s + (wid ? wsum[wid - 1] : 0);
#pragma unroll
    for (int j = 0; j < 16; j++) {
        int4 v = h4[tid * 16 + j];
        int4 o;
        o.x = run;
        o.y = run + v.x;
        o.z = run + v.x + v.y;
        o.w = run + v.x + v.y + v.z;
        reinterpret_cast<int4*>(g_binstart)[tid * 16 + j] = o;
        run += v.x + v.y + v.z + v.w;
    }
    if (tid == 1023) g_binstart[NB2] = run;
}

__global__ void scatter_kernel(const float* __restrict__ p, int n) {
    int i = blockIdx.x * blockDim.x + threadIdx.x;
    if (i < n) {
        float x = p[3 * i];
        float y = p[3 * i + 1];
        int key = (bin1(y) << 8) | bin1(x);
        int pos = g_binstart[key] + atomicAdd(&g_cnt[key], 1);
        g_sx[pos] = x;
        g_sy[pos] = y;
        g_ssq[pos] = fmaf(x, x, y * y);
        g_sorig[pos] = i;
    }
}

// ================= main kernel =================
__global__ void __launch_bounds__(1024, 1)
knn_grid_kernel(float* __restrict__ out, int n, int padn) {
    extern __shared__ float smem[];
    float* xs = smem;
    float* ys = smem + padn;
    float* sv = smem + 2 * padn;

    const int tid = threadIdx.x;
    for (int j = tid; j < padn; j += blockDim.x) {
        int slot = j - PAD;
        if (slot >= 0 && slot < n) {
            xs[j] = g_sx[slot];
            ys[j] = g_sy[slot];
            sv[j] = g_ssq[slot];
        } else {
            xs[j] = (slot < 0) ? -1.0e9f : 1.0e9f;
            ys[j] = 0.0f;
            sv[j] = RBIG;
        }
    }
    __syncthreads();

    const float* px = xs + PAD;
    const float* py = ys + PAD;
    const float* psq = sv + PAD;

    const int lane = tid & 31;
    const int gw = blockIdx.x * (blockDim.x >> 5) + (tid >> 5);
    const int nwarps = gridDim.x * (blockDim.x >> 5);

    for (int s = gw; s < n; s += nwarps) {
        const float xq = px[s];
        const float yq = py[s];
        const float sqq = psq[s];
        const float cx = -2.0f * xq;
        const float cy = -2.0f * yq;
        const unsigned long long cx2 = pack2(cx, cx);
        const unsigned long long cy2 = pack2(cy, cy);

        // ---- prime: bitonic top-32 over slot window [A, A+31] ----
        const int A = s - 16;
        const int Aend = A + 32;
        float lr;
        int li;
        {
            int cand = A + lane;
            float r = fmaf(cx, px[cand], fmaf(cy, py[cand], psq[cand]));
            if (cand == s) r = RBIG;
#pragma unroll
            for (int k = 2; k <= 32; k <<= 1) {
#pragma unroll
                for (int j = k >> 1; j > 0; j >>= 1) {
                    float orv = __shfl_xor_sync(FULLMASK, r, j);
                    int oiv = __shfl_xor_sync(FULLMASK, cand, j);
                    bool up = ((lane & k) == 0);
                    bool lower = ((lane & j) == 0);
                    bool takeMin = (lower == up);
                    bool sw = takeMin ? (orv < r) : (orv > r);
                    if (sw) { r = orv; cand = oiv; }
                }
            }
            lr = r;
            li = cand;
        }
        float worst = __shfl_sync(FULLMASK, lr, KNN - 1);
        // true-distance radius from r-space threshold (worst = d^2 - sqq)
        float rad = sqrtf(fmaxf(worst + sqq, 0.0f)) * 1.0001f + 1e-7f;

        // scan contiguous slot piece [a, b), masking invalid slots
        auto scan_piece = [&](int a, int b) {
            if (a >= b) return;
            const int a0 = a & ~1;
            for (int c = a0; c < b; c += 64) {
                const int c0 = c + 2 * lane;
                float2 xv = *reinterpret_cast<const float2*>(px + c0);
                float2 yv = *reinterpret_cast<const float2*>(py + c0);
                float2 qv = *reinterpret_cast<const float2*>(psq + c0);
                unsigned long long rr =
                    fma2(cx2, pack2(xv.x, xv.y),
                         fma2(cy2, pack2(yv.x, yv.y), pack2(qv.x, qv.y)));
                float r0, r1;
                unpack2(rr, r0, r1);
                if (c0 < a || c0 >= b) r0 = RBIG;
                if (c0 + 1 < a || c0 + 1 >= b) r1 = RBIG;

                unsigned hb = __ballot_sync(FULLMASK, fminf(r0, r1) < worst);
                if (hb) {
                    unsigned pm = (r0 < worst ? 1u : 0u) | (r1 < worst ? 2u : 0u);
                    float vs = (pm & 1u) ? r0 : r1;
                    int vis = c0 + ((pm & 1u) ? 0 : 1);
                    unsigned act = __ballot_sync(FULLMASK, pm != 0u);
                    while (act) {
                        int src = __ffs(act) - 1;
                        float val = __shfl_sync(FULLMASK, vs, src);
                        int vi = __shfl_sync(FULLMASK, vis, src);
                        if (lane == src) {
                            pm &= pm - 1u;
                            vs = r1;
                            vis = c0 + 1;
                        }
                        if (val < worst) {
                            bool cc = val < lr;
                            unsigned bal = __ballot_sync(FULLMASK, cc);
                            int pos = __ffs(bal) - 1;
                            float pr = __shfl_up_sync(FULLMASK, lr, 1);
                            int pi = __shfl_up_sync(FULLMASK, li, 1);
                            if (cc) {
                                lr = (lane == pos) ? val : pr;
                                li = (lane == pos) ? vi : pi;
                            }
                            worst = __shfl_sync(FULLMASK, lr, KNN - 1);
                        }
                        act = __ballot_sync(FULLMASK, pm != 0u);
                    }
                }
            }
        };

        // scan span minus the already-primed window [A, Aend)
        auto scan_span = [&](int a, int b) {
            scan_piece(a, min(b, A));
            scan_piece(max(a, Aend), b);
        };

        // scan one y-row restricted to x-bins within current radius
        auto scan_row = [&](int iy) {
            int bxlo = bin1(xq - rad);
            int bxhi = bin1(xq + rad);
            int base = iy << 8;
            int lo = __ldg(&g_binstart[base + bxlo]);
            int hi = __ldg(&g_binstart[base + bxhi + 1]);
            scan_span(lo, hi);
            rad = sqrtf(fmaxf(worst + sqq, 0.0f)) * 1.0001f + 1e-7f;
        };

        const int iyq = bin1(yq);
        scan_row(iyq);
        for (int t = 1;; t++) {
            bool any = false;
            int ru = iyq + t;
            if (ru < GB && yq + rad > XLO + (float)ru * BINW) {
                scan_row(ru);
                any = true;
            }
            int rd = iyq - t;
            if (rd >= 0 && yq - rad < XLO + (float)(rd + 1) * BINW) {
                scan_row(rd);
                any = true;
            }
            if (!any) break;
        }

        // ---- epilogue: exact distances, scatter to original row ----
        float dx = xq - px[li];
        float dy = yq - py[li];
        float d = sqrtf(dx * dx + dy * dy);
        int orig = g_sorig[s];
        if (lane < KNN) out[orig * KNN + lane] = d;
    }
}

extern "C" void kernel_launch(void* const* d_in, const int* in_sizes, int n_in,
                              void* d_out, int out_size) {
    const float* p = (const float*)d_in[0];
    float* out = (float*)d_out;
    int n = in_sizes[0] / 3;

    int nb = (n + 1023) / 1024;
    zero_kernel<<<(NB2 + 1023) / 1024, 1024>>>();
    hist_kernel<<<nb, 1024>>>(p, n);
    prefix_kernel<<<1, 1024>>>();
    scatter_kernel<<<nb, 1024>>>(p, n);

    int padn = n + 2 * PAD;
    size_t smem = (size_t)3 * padn * sizeof(float);
    cudaFuncSetAttribute(knn_grid_kernel,
                         cudaFuncAttributeMaxDynamicSharedMemorySize, (int)smem);
    knn_grid_kernel<<<152, 1024, smem>>>(out, n, padn);
}